// round 1
// baseline (speedup 1.0000x reference)
#include <cuda_runtime.h>

#define NN 100000
#define NE 1600000
#define DIN 128
#define HID 64
#define NG 512
#define NC 10

// Scratch (device globals; allocation is forbidden). 16B-aligned for float4/red.v4.
__device__ __align__(16) float g_deg[NN];
__device__ __align__(16) float g_dinv[NN];
__device__ __align__(16) float g_h[NN * HID];
__device__ __align__(16) float g_agg[NN * HID];
__device__ __align__(16) float g_pool[NG * HID];
__device__ __align__(16) float g_cnt[NG];

// ---------------------------------------------------------------------------
// degree: deg[dst] += 1 over all edges (RED, no return)
__global__ void k_deg(const int* __restrict__ ei) {
    int e = blockIdx.x * blockDim.x + threadIdx.x;
    if (e < NE) atomicAdd(&g_deg[ei[NE + e]], 1.0f);
}

__global__ void k_dinv() {
    int n = blockIdx.x * blockDim.x + threadIdx.x;
    if (n < NN) g_dinv[n] = rsqrtf(g_deg[n] + 1.0f);  // +1 self-loop
}

// ---------------------------------------------------------------------------
// h = x @ W1   (x: [NN,128], W1: [128,64])  — one warp per node, W1 in SMEM
__global__ void k_gemm1(const float* __restrict__ x, const float* __restrict__ W1) {
    __shared__ float Ws[DIN * HID];
    for (int i = threadIdx.x; i < DIN * HID; i += blockDim.x) Ws[i] = W1[i];
    __syncthreads();
    int warp = threadIdx.x >> 5, lane = threadIdx.x & 31;
    int node = blockIdx.x * 8 + warp;
    if (node >= NN) return;
    const float* xr = x + (size_t)node * DIN;
    float xv[4];
#pragma unroll
    for (int r = 0; r < 4; r++) xv[r] = xr[r * 32 + lane];
    float a0 = 0.f, a1 = 0.f;
#pragma unroll
    for (int r = 0; r < 4; r++) {
#pragma unroll
        for (int kk = 0; kk < 32; kk++) {
            float xk = __shfl_sync(0xffffffffu, xv[r], kk);
            int k = r * 32 + kk;
            a0 += xk * Ws[k * HID + lane];
            a1 += xk * Ws[k * HID + lane + 32];
        }
    }
    g_h[(size_t)node * HID + lane]      = a0;
    g_h[(size_t)node * HID + lane + 32] = a1;
}

// h = relu1(agg) @ W2   (input lives in g_agg after k_act, output -> g_h)
__global__ void k_gemm2(const float* __restrict__ W2) {
    __shared__ float Ws[HID * HID];
    for (int i = threadIdx.x; i < HID * HID; i += blockDim.x) Ws[i] = W2[i];
    __syncthreads();
    int warp = threadIdx.x >> 5, lane = threadIdx.x & 31;
    int node = blockIdx.x * 8 + warp;
    if (node >= NN) return;
    const float* xr = g_agg + (size_t)node * HID;
    float xv0 = xr[lane], xv1 = xr[32 + lane];
    float a0 = 0.f, a1 = 0.f;
#pragma unroll
    for (int kk = 0; kk < 32; kk++) {
        float xk = __shfl_sync(0xffffffffu, xv0, kk);
        a0 += xk * Ws[kk * HID + lane];
        a1 += xk * Ws[kk * HID + lane + 32];
    }
#pragma unroll
    for (int kk = 0; kk < 32; kk++) {
        float xk = __shfl_sync(0xffffffffu, xv1, kk);
        a0 += xk * Ws[(32 + kk) * HID + lane];
        a1 += xk * Ws[(32 + kk) * HID + lane + 32];
    }
    g_h[(size_t)node * HID + lane]      = a0;
    g_h[(size_t)node * HID + lane + 32] = a1;
}

// ---------------------------------------------------------------------------
// edge aggregation: agg[dst] += h[src] * dinv[src]*dinv[dst]
// 16 lanes per edge; each lane moves one float4 (coalesced row gather + red.v4)
__global__ void k_agg(const int* __restrict__ ei) {
    int t = blockIdx.x * blockDim.x + threadIdx.x;   // NE*16 threads exactly
    int lane = threadIdx.x & 31;
    int e = t >> 4;
    int j = lane & 15;
    int sub = lane >> 4;
    int src = 0, dst = 0;
    float coef = 0.f;
    if (j == 0) {
        src = ei[e];
        dst = ei[NE + e];
        coef = g_dinv[src] * g_dinv[dst];
    }
    src  = __shfl_sync(0xffffffffu, src,  sub << 4);
    dst  = __shfl_sync(0xffffffffu, dst,  sub << 4);
    coef = __shfl_sync(0xffffffffu, coef, sub << 4);

    const float4* h4 = (const float4*)g_h;
    float4 v = __ldg(h4 + (size_t)src * 16 + j);
    float4* a4 = (float4*)g_agg + (size_t)dst * 16 + j;
    asm volatile("red.global.add.v4.f32 [%0], {%1, %2, %3, %4};"
                 :: "l"(a4), "f"(v.x * coef), "f"(v.y * coef),
                    "f"(v.z * coef), "f"(v.w * coef)
                 : "memory");
}

// in-place: agg = relu(agg + h * dinv^2 + bias)
__global__ void k_act(const float* __restrict__ bias) {
    int t = blockIdx.x * blockDim.x + threadIdx.x;   // NN*16 threads exactly
    int node = t >> 4, j = t & 15;
    float di = g_dinv[node];
    float c = di * di;
    float4 a = ((float4*)g_agg)[t];
    float4 h = ((const float4*)g_h)[t];
    float4 b = ((const float4*)bias)[j];
    float4 r;
    r.x = fmaxf(a.x + h.x * c + b.x, 0.f);
    r.y = fmaxf(a.y + h.y * c + b.y, 0.f);
    r.z = fmaxf(a.z + h.z * c + b.z, 0.f);
    r.w = fmaxf(a.w + h.w * c + b.w, 0.f);
    ((float4*)g_agg)[t] = r;
}

// ---------------------------------------------------------------------------
// global mean pool numerator/denominator via red
__global__ void k_pool(const int* __restrict__ batch) {
    int t = blockIdx.x * blockDim.x + threadIdx.x;   // NN*16 threads exactly
    int node = t >> 4, j = t & 15;
    int g = batch[node];
    float4 v = ((const float4*)g_agg)[t];
    float4* p = (float4*)g_pool + (size_t)g * 16 + j;
    asm volatile("red.global.add.v4.f32 [%0], {%1, %2, %3, %4};"
                 :: "l"(p), "f"(v.x), "f"(v.y), "f"(v.z), "f"(v.w)
                 : "memory");
    if (j == 0) atomicAdd(&g_cnt[g], 1.0f);
}

// logits = (pool/cnt) @ Wfc + bfc, then log_softmax. One thread per graph.
__global__ void k_head(const float* __restrict__ Wfc, const float* __restrict__ bfc,
                       float* __restrict__ out) {
    __shared__ float Wf[HID * NC];
    __shared__ float bf[NC];
    for (int i = threadIdx.x; i < HID * NC; i += blockDim.x) Wf[i] = Wfc[i];
    if (threadIdx.x < NC) bf[threadIdx.x] = bfc[threadIdx.x];
    __syncthreads();
    int g = blockIdx.x * blockDim.x + threadIdx.x;
    if (g >= NG) return;
    float inv = 1.0f / fmaxf(g_cnt[g], 1.0f);
    float l[NC];
#pragma unroll
    for (int j = 0; j < NC; j++) l[j] = bf[j];
    for (int k = 0; k < HID; k++) {
        float pv = g_pool[g * HID + k] * inv;
#pragma unroll
        for (int j = 0; j < NC; j++) l[j] += pv * Wf[k * NC + j];
    }
    float m = l[0];
#pragma unroll
    for (int j = 1; j < NC; j++) m = fmaxf(m, l[j]);
    float s = 0.f;
#pragma unroll
    for (int j = 0; j < NC; j++) s += expf(l[j] - m);
    float lse = m + logf(s);
#pragma unroll
    for (int j = 0; j < NC; j++) out[g * NC + j] = l[j] - lse;
}

// ---------------------------------------------------------------------------
extern "C" void kernel_launch(void* const* d_in, const int* in_sizes, int n_in,
                              void* d_out, int out_size) {
    const float* x    = (const float*)d_in[0];
    const int*   ei   = (const int*)d_in[1];
    const int*   batch= (const int*)d_in[2];
    const float* W1   = (const float*)d_in[3];
    const float* b1   = (const float*)d_in[4];
    const float* W2   = (const float*)d_in[5];
    const float* b2   = (const float*)d_in[6];
    const float* Wfc  = (const float*)d_in[7];
    const float* bfc  = (const float*)d_in[8];
    float* out = (float*)d_out;

    void *p_deg, *p_agg, *p_pool, *p_cnt;
    cudaGetSymbolAddress(&p_deg,  g_deg);
    cudaGetSymbolAddress(&p_agg,  g_agg);
    cudaGetSymbolAddress(&p_pool, g_pool);
    cudaGetSymbolAddress(&p_cnt,  g_cnt);

    // degrees + normalization
    cudaMemsetAsync(p_deg, 0, NN * sizeof(float));
    k_deg<<<(NE + 255) / 256, 256>>>(ei);
    k_dinv<<<(NN + 255) / 256, 256>>>();

    // layer 1
    k_gemm1<<<(NN + 7) / 8, 256>>>(x, W1);
    cudaMemsetAsync(p_agg, 0, (size_t)NN * HID * sizeof(float));
    k_agg<<<(NE * 16) / 256, 256>>>(ei);
    k_act<<<(NN * 16) / 256, 256>>>(b1);

    // layer 2
    k_gemm2<<<(NN + 7) / 8, 256>>>(W2);
    cudaMemsetAsync(p_agg, 0, (size_t)NN * HID * sizeof(float));
    k_agg<<<(NE * 16) / 256, 256>>>(ei);
    k_act<<<(NN * 16) / 256, 256>>>(b2);

    // pool + head
    cudaMemsetAsync(p_pool, 0, NG * HID * sizeof(float));
    cudaMemsetAsync(p_cnt,  0, NG * sizeof(float));
    k_pool<<<(NN * 16) / 256, 256>>>(batch);
    k_head<<<(NG + 255) / 256, 256>>>(Wfc, bfc, out);
}

// round 5
// speedup vs baseline: 1.7584x; 1.7584x over previous
#include <cuda_runtime.h>

#define NN 100000
#define NE 1600000
#define DIN 128
#define HID 64
#define NG 512
#define NC 10

// ---------------- scratch (device globals; no allocation allowed) ----------
__device__ __align__(16) float g_h[NN * HID];     // dense features (gemm out)
__device__ __align__(16) float g_a[NN * HID];     // aggregated/activated
__device__ __align__(16) float g_pool[NG * HID];
__device__ float g_dinv[NN];
__device__ int   g_degi[NN];
__device__ int   g_ptr[NN + 1];
__device__ int   g_pos[NN];
__device__ int   g_gcnt[NG];
__device__ __align__(16) int g_esrc[NE];

// ---------------- histograms ----------------------------------------------
__global__ void k_deg(const int* __restrict__ ei) {
    int e = blockIdx.x * blockDim.x + threadIdx.x;
    if (e < NE) atomicAdd(&g_degi[ei[NE + e]], 1);
}

__global__ void k_gcnt(const int* __restrict__ batch) {
    int n = blockIdx.x * blockDim.x + threadIdx.x;
    if (n < NN) atomicAdd(&g_gcnt[batch[n]], 1);
}

// single-block exclusive scan of g_degi -> g_ptr/g_pos, plus dinv
__global__ void k_scan() {
    __shared__ int partial[1024];
    const int CH = (NN + 1023) / 1024;
    int t = threadIdx.x;
    int base = t * CH;
    int s = 0;
    for (int i = 0; i < CH; i++) {
        int idx = base + i;
        if (idx < NN) s += g_degi[idx];
    }
    partial[t] = s;
    __syncthreads();
    for (int off = 1; off < 1024; off <<= 1) {
        int v = (t >= off) ? partial[t - off] : 0;
        __syncthreads();
        partial[t] += v;
        __syncthreads();
    }
    int run = (t == 0) ? 0 : partial[t - 1];
    for (int i = 0; i < CH; i++) {
        int idx = base + i;
        if (idx < NN) {
            g_ptr[idx] = run;
            g_pos[idx] = run;
            int d = g_degi[idx];
            run += d;
            g_dinv[idx] = rsqrtf((float)d + 1.0f);
        }
    }
    if (t == 0) g_ptr[NN] = NE;
}

__global__ void k_scatter(const int* __restrict__ ei) {
    int e = blockIdx.x * blockDim.x + threadIdx.x;
    if (e >= NE) return;
    int src = __ldg(&ei[e]);
    int dst = __ldg(&ei[NE + e]);
    int p = atomicAdd(&g_pos[dst], 1);
    g_esrc[p] = src;
}

// ---------------- tiled register-blocked GEMM ------------------------------
// C[64 nodes x 64 cols] per block; 256 threads; thread (i,j) computes 4x4.
template <int K, int LDX>
__global__ void k_gemm(const float* __restrict__ X, const float* __restrict__ W,
                       float* __restrict__ Y) {
    const int STRIDE = 68;
    __shared__ __align__(16) float xs_t[32 * STRIDE];   // [kk][node]
    __shared__ __align__(16) float Ws[32 * 64];         // [kk][col]
    int t = threadIdx.x;
    int i = t >> 4, j = t & 15;
    int node0 = blockIdx.x * 64;
    float acc[4][4];
#pragma unroll
    for (int r = 0; r < 4; r++)
#pragma unroll
        for (int c = 0; c < 4; c++) acc[r][c] = 0.f;

    for (int k0 = 0; k0 < K; k0 += 32) {
#pragma unroll
        for (int q = 0; q < 2; q++) {
            int idx4 = t + q * 256;
            int row = idx4 >> 3, c4 = idx4 & 7;
            int node = node0 + row;
            if (node >= NN) node = NN - 1;
            float4 v = *(const float4*)&X[(size_t)node * LDX + k0 + c4 * 4];
            xs_t[(c4 * 4 + 0) * STRIDE + row] = v.x;
            xs_t[(c4 * 4 + 1) * STRIDE + row] = v.y;
            xs_t[(c4 * 4 + 2) * STRIDE + row] = v.z;
            xs_t[(c4 * 4 + 3) * STRIDE + row] = v.w;
        }
#pragma unroll
        for (int q = 0; q < 2; q++) {
            int idx4 = t + q * 256;
            int kk = idx4 >> 4, c = idx4 & 15;
            ((float4*)Ws)[kk * 16 + c] = ((const float4*)W)[(k0 + kk) * 16 + c];
        }
        __syncthreads();
#pragma unroll
        for (int kk = 0; kk < 32; kk++) {
            float4 a = *(const float4*)&xs_t[kk * STRIDE + i * 4];
            float4 b = ((const float4*)Ws)[kk * 16 + j];
            acc[0][0] += a.x * b.x; acc[0][1] += a.x * b.y; acc[0][2] += a.x * b.z; acc[0][3] += a.x * b.w;
            acc[1][0] += a.y * b.x; acc[1][1] += a.y * b.y; acc[1][2] += a.y * b.z; acc[1][3] += a.y * b.w;
            acc[2][0] += a.z * b.x; acc[2][1] += a.z * b.y; acc[2][2] += a.z * b.z; acc[2][3] += a.z * b.w;
            acc[3][0] += a.w * b.x; acc[3][1] += a.w * b.y; acc[3][2] += a.w * b.z; acc[3][3] += a.w * b.w;
        }
        __syncthreads();
    }
#pragma unroll
    for (int r = 0; r < 4; r++) {
        int node = node0 + i * 4 + r;
        if (node < NN) {
            float4 v = make_float4(acc[r][0], acc[r][1], acc[r][2], acc[r][3]);
            *(float4*)&Y[(size_t)node * HID + j * 4] = v;
        }
    }
}

// ---------------- CSR aggregation (warp per node) --------------------------
// out = relu( sum_{e->n} h[src]*dinv[src]*dinv[n] + h[n]*dinv[n]^2 + bias )
// POOL: additionally RED raw out into g_pool (divide by count in head).
template <bool POOL>
__global__ void k_aggcsr(const float* __restrict__ bias,
                         const int* __restrict__ batch) {
    int warp = threadIdx.x >> 5, lane = threadIdx.x & 31;
    int j = lane & 15, sub = lane >> 4;
    int node = blockIdx.x * 8 + warp;
    if (node >= NN) return;
    int start = __ldg(&g_ptr[node]);
    int end   = __ldg(&g_ptr[node + 1]);
    float dn = __ldg(&g_dinv[node]);
    const float4* h4 = (const float4*)g_h;
    float4 acc = make_float4(0.f, 0.f, 0.f, 0.f);
    for (int p = start + sub; p < end; p += 2) {
        int src  = __ldg(&g_esrc[p]);
        float cf = __ldg(&g_dinv[src]) * dn;
        float4 v = __ldg(h4 + (size_t)src * 16 + j);
        acc.x += v.x * cf; acc.y += v.y * cf; acc.z += v.z * cf; acc.w += v.w * cf;
    }
    acc.x += __shfl_down_sync(0xffffffffu, acc.x, 16);
    acc.y += __shfl_down_sync(0xffffffffu, acc.y, 16);
    acc.z += __shfl_down_sync(0xffffffffu, acc.z, 16);
    acc.w += __shfl_down_sync(0xffffffffu, acc.w, 16);
    if (sub == 0) {
        float c = dn * dn;
        float4 h = __ldg(h4 + (size_t)node * 16 + j);
        float4 b = __ldg((const float4*)bias + j);
        float4 r;
        r.x = fmaxf(acc.x + h.x * c + b.x, 0.f);
        r.y = fmaxf(acc.y + h.y * c + b.y, 0.f);
        r.z = fmaxf(acc.z + h.z * c + b.z, 0.f);
        r.w = fmaxf(acc.w + h.w * c + b.w, 0.f);
        if (POOL) {
            int g = __ldg(&batch[node]);
            float4* p4 = (float4*)g_pool + (size_t)g * 16 + j;
            asm volatile("red.global.add.v4.f32 [%0], {%1, %2, %3, %4};"
                         :: "l"(p4), "f"(r.x), "f"(r.y), "f"(r.z), "f"(r.w)
                         : "memory");
        } else {
            *((float4*)g_a + (size_t)node * 16 + j) = r;
        }
    }
}

// ---------------- head -----------------------------------------------------
__global__ void k_head(const float* __restrict__ Wfc, const float* __restrict__ bfc,
                       float* __restrict__ out) {
    __shared__ float Wf[HID * NC];
    __shared__ float bf[NC];
    for (int i = threadIdx.x; i < HID * NC; i += blockDim.x) Wf[i] = Wfc[i];
    if (threadIdx.x < NC) bf[threadIdx.x] = bfc[threadIdx.x];
    __syncthreads();
    int g = blockIdx.x * blockDim.x + threadIdx.x;
    if (g >= NG) return;
    float inv = 1.0f / fmaxf((float)g_gcnt[g], 1.0f);
    float l[NC];
#pragma unroll
    for (int j = 0; j < NC; j++) l[j] = bf[j];
    for (int k = 0; k < HID; k++) {
        float pv = g_pool[g * HID + k] * inv;
#pragma unroll
        for (int j = 0; j < NC; j++) l[j] += pv * Wf[k * NC + j];
    }
    float m = l[0];
#pragma unroll
    for (int j = 1; j < NC; j++) m = fmaxf(m, l[j]);
    float s = 0.f;
#pragma unroll
    for (int j = 0; j < NC; j++) s += expf(l[j] - m);
    float lse = m + logf(s);
#pragma unroll
    for (int j = 0; j < NC; j++) out[g * NC + j] = l[j] - lse;
}

// ---------------------------------------------------------------------------
extern "C" void kernel_launch(void* const* d_in, const int* in_sizes, int n_in,
                              void* d_out, int out_size) {
    const float* x     = (const float*)d_in[0];
    const int*   ei    = (const int*)d_in[1];
    const int*   batch = (const int*)d_in[2];
    const float* W1    = (const float*)d_in[3];
    const float* b1    = (const float*)d_in[4];
    const float* W2    = (const float*)d_in[5];
    const float* b2    = (const float*)d_in[6];
    const float* Wfc   = (const float*)d_in[7];
    const float* bfc   = (const float*)d_in[8];
    float* out = (float*)d_out;

    // Resolve REAL device addresses of the scratch globals. Passing the bare
    // symbols as kernel args from host code silently hands the kernels the
    // host shadow address (ATS makes it dereferenceable on GB300) — that was
    // the R2/R4 correctness bug.
    void *p_degi, *p_gcnt, *p_pool, *p_h, *p_a;
    cudaGetSymbolAddress(&p_degi, g_degi);
    cudaGetSymbolAddress(&p_gcnt, g_gcnt);
    cudaGetSymbolAddress(&p_pool, g_pool);
    cudaGetSymbolAddress(&p_h,    g_h);
    cudaGetSymbolAddress(&p_a,    g_a);
    float* dh = (float*)p_h;
    float* da = (float*)p_a;

    cudaMemsetAsync(p_degi, 0, NN * sizeof(int));
    cudaMemsetAsync(p_gcnt, 0, NG * sizeof(int));
    cudaMemsetAsync(p_pool, 0, NG * HID * sizeof(float));

    // CSR build
    k_deg<<<(NE + 255) / 256, 256>>>(ei);
    k_gcnt<<<(NN + 255) / 256, 256>>>(batch);
    k_scan<<<1, 1024>>>();
    k_scatter<<<(NE + 255) / 256, 256>>>(ei);

    // layer 1
    k_gemm<DIN, DIN><<<(NN + 63) / 64, 256>>>(x, W1, dh);
    k_aggcsr<false><<<(NN + 7) / 8, 256>>>(b1, batch);

    // layer 2 (+ fused raw-sum pool)
    k_gemm<HID, HID><<<(NN + 63) / 64, 256>>>(da, W2, dh);
    k_aggcsr<true><<<(NN + 7) / 8, 256>>>(b2, batch);

    // head (divides pool sums by counts)
    k_head<<<1, NG>>>(Wfc, bfc, out);
}

// round 6
// speedup vs baseline: 3.2875x; 1.8696x over previous
#include <cuda_runtime.h>

#define NN 100000
#define NE 1600000
#define DIN 128
#define HID 64
#define NG 512
#define NC 10

#define GEMM1_BLKS ((NN + 63) / 64)          // 1563
#define DEG_BLKS   ((NE + 255) / 256)        // 6250
#define GCNT_BLKS  ((NN + 255) / 256)        // 391
#define SCAN_BLKS  ((NN + 1023) / 1024)      // 98

// ---------------- scratch (device globals; no allocation allowed) ----------
__device__ __align__(16) float g_h[NN * HID];
__device__ __align__(16) float g_a[NN * HID];
__device__ __align__(16) float g_pool[NG * HID];
__device__ float g_dinv[NN];
__device__ int   g_degi[NN];
__device__ int   g_ptr[NN + 1];
__device__ int   g_pos[NN];
__device__ int   g_gcnt[NG];
__device__ int   g_bsum[SCAN_BLKS];
__device__ int   g_boff[SCAN_BLKS];
__device__ __align__(16) int   g_esrc[NE];
__device__ __align__(16) float g_ecoef[NE];

// ---------------- GEMM body (device; used by front kernel and k_gemm) ------
template <int K, int LDX>
__device__ __forceinline__ void gemm_body(const float* __restrict__ X,
                                          const float* __restrict__ W,
                                          float* __restrict__ Y, int blk) {
    const int STRIDE = 68;
    __shared__ __align__(16) float xs_t[32 * STRIDE];
    __shared__ __align__(16) float Ws[32 * 64];
    int t = threadIdx.x;
    int i = t >> 4, j = t & 15;
    int node0 = blk * 64;
    float acc[4][4];
#pragma unroll
    for (int r = 0; r < 4; r++)
#pragma unroll
        for (int c = 0; c < 4; c++) acc[r][c] = 0.f;

    for (int k0 = 0; k0 < K; k0 += 32) {
#pragma unroll
        for (int q = 0; q < 2; q++) {
            int idx4 = t + q * 256;
            int row = idx4 >> 3, c4 = idx4 & 7;
            int node = node0 + row;
            if (node >= NN) node = NN - 1;
            float4 v = *(const float4*)&X[(size_t)node * LDX + k0 + c4 * 4];
            xs_t[(c4 * 4 + 0) * STRIDE + row] = v.x;
            xs_t[(c4 * 4 + 1) * STRIDE + row] = v.y;
            xs_t[(c4 * 4 + 2) * STRIDE + row] = v.z;
            xs_t[(c4 * 4 + 3) * STRIDE + row] = v.w;
        }
#pragma unroll
        for (int q = 0; q < 2; q++) {
            int idx4 = t + q * 256;
            int kk = idx4 >> 4, c = idx4 & 15;
            ((float4*)Ws)[kk * 16 + c] = ((const float4*)W)[(k0 + kk) * 16 + c];
        }
        __syncthreads();
#pragma unroll
        for (int kk = 0; kk < 32; kk++) {
            float4 a = *(const float4*)&xs_t[kk * STRIDE + i * 4];
            float4 b = ((const float4*)Ws)[kk * 16 + j];
            acc[0][0] += a.x * b.x; acc[0][1] += a.x * b.y; acc[0][2] += a.x * b.z; acc[0][3] += a.x * b.w;
            acc[1][0] += a.y * b.x; acc[1][1] += a.y * b.y; acc[1][2] += a.y * b.z; acc[1][3] += a.y * b.w;
            acc[2][0] += a.z * b.x; acc[2][1] += a.z * b.y; acc[2][2] += a.z * b.z; acc[2][3] += a.z * b.w;
            acc[3][0] += a.w * b.x; acc[3][1] += a.w * b.y; acc[3][2] += a.w * b.z; acc[3][3] += a.w * b.w;
        }
        __syncthreads();
    }
#pragma unroll
    for (int r = 0; r < 4; r++) {
        int node = node0 + i * 4 + r;
        if (node < NN) {
            float4 v = make_float4(acc[r][0], acc[r][1], acc[r][2], acc[r][3]);
            *(float4*)&Y[(size_t)node * HID + j * 4] = v;
        }
    }
}

// ---------------- fused front: gemm1 | degree histogram | graph histogram --
__global__ void k_front(const float* __restrict__ x, const float* __restrict__ W1,
                        const int* __restrict__ ei, const int* __restrict__ batch,
                        float* __restrict__ Y) {
    int b = blockIdx.x;
    if (b < GEMM1_BLKS) {
        gemm_body<DIN, DIN>(x, W1, Y, b);
    } else if (b < GEMM1_BLKS + DEG_BLKS) {
        int e = (b - GEMM1_BLKS) * 256 + threadIdx.x;
        if (e < NE) atomicAdd(&g_degi[ei[NE + e]], 1);
    } else {
        int n = (b - GEMM1_BLKS - DEG_BLKS) * 256 + threadIdx.x;
        if (n < NN) atomicAdd(&g_gcnt[batch[n]], 1);
    }
}

// ---------------- 3-phase parallel scan ------------------------------------
__global__ void k_scan1() {        // per-block sums of degi
    __shared__ int wsum[32];
    int b = blockIdx.x, t = threadIdx.x;
    int idx = b * 1024 + t;
    int d = (idx < NN) ? g_degi[idx] : 0;
    int v = d;
#pragma unroll
    for (int o = 16; o > 0; o >>= 1) v += __shfl_down_sync(0xffffffffu, v, o);
    if ((t & 31) == 0) wsum[t >> 5] = v;
    __syncthreads();
    if (t < 32) {
        int s = wsum[t];
#pragma unroll
        for (int o = 16; o > 0; o >>= 1) s += __shfl_down_sync(0xffffffffu, s, o);
        if (t == 0) g_bsum[b] = s;
    }
}

__global__ void k_scan2() {        // exclusive scan of 98 block sums (1 block)
    __shared__ int s[SCAN_BLKS];
    int t = threadIdx.x;
    if (t < SCAN_BLKS) s[t] = g_bsum[t];
    __syncthreads();
    if (t == 0) {
        int run = 0;
        for (int i = 0; i < SCAN_BLKS; i++) { int v = s[i]; s[i] = run; run += v; }
    }
    __syncthreads();
    if (t < SCAN_BLKS) g_boff[t] = s[t];
}

__global__ void k_scan3() {        // local exclusive scan + offset; dinv; pos
    __shared__ int sd[1024];
    int b = blockIdx.x, t = threadIdx.x;
    int idx = b * 1024 + t;
    int d = (idx < NN) ? g_degi[idx] : 0;
    sd[t] = d;
    __syncthreads();
    for (int off = 1; off < 1024; off <<= 1) {
        int v = (t >= off) ? sd[t - off] : 0;
        __syncthreads();
        sd[t] += v;
        __syncthreads();
    }
    if (idx < NN) {
        int excl = sd[t] - d + g_boff[b];
        g_ptr[idx] = excl;
        g_pos[idx] = excl;
        g_dinv[idx] = rsqrtf((float)d + 1.0f);
    }
    if (b == SCAN_BLKS - 1 && t == 0) g_ptr[NN] = NE;
}

__global__ void k_scatter(const int* __restrict__ ei) {
    int e = blockIdx.x * blockDim.x + threadIdx.x;
    if (e >= NE) return;
    int src = __ldg(&ei[e]);
    int dst = __ldg(&ei[NE + e]);
    int p = atomicAdd(&g_pos[dst], 1);
    g_esrc[p] = src;
    g_ecoef[p] = __ldg(&g_dinv[src]) * __ldg(&g_dinv[dst]);
}

// ---------------- layer-2 GEMM wrapper -------------------------------------
__global__ void k_gemm2(const float* __restrict__ X, const float* __restrict__ W,
                        float* __restrict__ Y) {
    gemm_body<HID, HID>(X, W, Y, blockIdx.x);
}

// ---------------- CSR aggregation (warp per node, 2x unrolled) -------------
template <bool POOL>
__global__ void k_aggcsr(const float* __restrict__ bias,
                         const int* __restrict__ batch) {
    int warp = threadIdx.x >> 5, lane = threadIdx.x & 31;
    int j = lane & 15, sub = lane >> 4;
    int node = blockIdx.x * 8 + warp;
    if (node >= NN) return;
    int start = __ldg(&g_ptr[node]);
    int end   = __ldg(&g_ptr[node + 1]);
    const float4* h4 = (const float4*)g_h;
    float4 a0 = make_float4(0.f, 0.f, 0.f, 0.f);
    float4 a1 = make_float4(0.f, 0.f, 0.f, 0.f);
    int p = start + sub;
    for (; p + 2 < end; p += 4) {
        int   s0 = __ldg(&g_esrc[p]);
        int   s1 = __ldg(&g_esrc[p + 2]);
        float c0 = __ldg(&g_ecoef[p]);
        float c1 = __ldg(&g_ecoef[p + 2]);
        float4 v0 = __ldg(h4 + (size_t)s0 * 16 + j);
        float4 v1 = __ldg(h4 + (size_t)s1 * 16 + j);
        a0.x += v0.x * c0; a0.y += v0.y * c0; a0.z += v0.z * c0; a0.w += v0.w * c0;
        a1.x += v1.x * c1; a1.y += v1.y * c1; a1.z += v1.z * c1; a1.w += v1.w * c1;
    }
    if (p < end) {
        int   s0 = __ldg(&g_esrc[p]);
        float c0 = __ldg(&g_ecoef[p]);
        float4 v0 = __ldg(h4 + (size_t)s0 * 16 + j);
        a0.x += v0.x * c0; a0.y += v0.y * c0; a0.z += v0.z * c0; a0.w += v0.w * c0;
    }
    a0.x += a1.x; a0.y += a1.y; a0.z += a1.z; a0.w += a1.w;
    a0.x += __shfl_down_sync(0xffffffffu, a0.x, 16);
    a0.y += __shfl_down_sync(0xffffffffu, a0.y, 16);
    a0.z += __shfl_down_sync(0xffffffffu, a0.z, 16);
    a0.w += __shfl_down_sync(0xffffffffu, a0.w, 16);
    if (sub == 0) {
        float dn = __ldg(&g_dinv[node]);
        float c = dn * dn;
        float4 h = __ldg(h4 + (size_t)node * 16 + j);
        float4 b = __ldg((const float4*)bias + j);
        float4 r;
        r.x = fmaxf(a0.x + h.x * c + b.x, 0.f);
        r.y = fmaxf(a0.y + h.y * c + b.y, 0.f);
        r.z = fmaxf(a0.z + h.z * c + b.z, 0.f);
        r.w = fmaxf(a0.w + h.w * c + b.w, 0.f);
        if (POOL) {
            int g = __ldg(&batch[node]);
            float4* p4 = (float4*)g_pool + (size_t)g * 16 + j;
            asm volatile("red.global.add.v4.f32 [%0], {%1, %2, %3, %4};"
                         :: "l"(p4), "f"(r.x), "f"(r.y), "f"(r.z), "f"(r.w)
                         : "memory");
        } else {
            *((float4*)g_a + (size_t)node * 16 + j) = r;
        }
    }
}

// ---------------- head -----------------------------------------------------
__global__ void k_head(const float* __restrict__ Wfc, const float* __restrict__ bfc,
                       float* __restrict__ out) {
    __shared__ float Wf[HID * NC];
    __shared__ float bf[NC];
    for (int i = threadIdx.x; i < HID * NC; i += blockDim.x) Wf[i] = Wfc[i];
    if (threadIdx.x < NC) bf[threadIdx.x] = bfc[threadIdx.x];
    __syncthreads();
    int g = blockIdx.x * blockDim.x + threadIdx.x;
    if (g >= NG) return;
    float inv = 1.0f / fmaxf((float)g_gcnt[g], 1.0f);
    float l[NC];
#pragma unroll
    for (int j = 0; j < NC; j++) l[j] = bf[j];
    for (int k = 0; k < HID; k++) {
        float pv = g_pool[g * HID + k] * inv;
#pragma unroll
        for (int j = 0; j < NC; j++) l[j] += pv * Wf[k * NC + j];
    }
    float m = l[0];
#pragma unroll
    for (int j = 1; j < NC; j++) m = fmaxf(m, l[j]);
    float s = 0.f;
#pragma unroll
    for (int j = 0; j < NC; j++) s += expf(l[j] - m);
    float lse = m + logf(s);
#pragma unroll
    for (int j = 0; j < NC; j++) out[g * NC + j] = l[j] - lse;
}

// ---------------------------------------------------------------------------
extern "C" void kernel_launch(void* const* d_in, const int* in_sizes, int n_in,
                              void* d_out, int out_size) {
    const float* x     = (const float*)d_in[0];
    const int*   ei    = (const int*)d_in[1];
    const int*   batch = (const int*)d_in[2];
    const float* W1    = (const float*)d_in[3];
    const float* b1    = (const float*)d_in[4];
    const float* W2    = (const float*)d_in[5];
    const float* b2    = (const float*)d_in[6];
    const float* Wfc   = (const float*)d_in[7];
    const float* bfc   = (const float*)d_in[8];
    float* out = (float*)d_out;

    // Resolve REAL device addresses (host shadow symbols are a silent trap on
    // GB300 — ATS makes them dereferenceable host memory).
    void *p_degi, *p_gcnt, *p_pool, *p_h, *p_a;
    cudaGetSymbolAddress(&p_degi, g_degi);
    cudaGetSymbolAddress(&p_gcnt, g_gcnt);
    cudaGetSymbolAddress(&p_pool, g_pool);
    cudaGetSymbolAddress(&p_h,    g_h);
    cudaGetSymbolAddress(&p_a,    g_a);
    float* dh = (float*)p_h;
    float* da = (float*)p_a;

    cudaMemsetAsync(p_degi, 0, NN * sizeof(int));
    cudaMemsetAsync(p_gcnt, 0, NG * sizeof(int));
    cudaMemsetAsync(p_pool, 0, NG * HID * sizeof(float));

    // fused: gemm1 + degree histogram + graph histogram (independent work)
    k_front<<<GEMM1_BLKS + DEG_BLKS + GCNT_BLKS, 256>>>(x, W1, ei, batch, dh);

    // parallel scan -> CSR pointers; scatter src + coef
    k_scan1<<<SCAN_BLKS, 1024>>>();
    k_scan2<<<1, 128>>>();
    k_scan3<<<SCAN_BLKS, 1024>>>();
    k_scatter<<<DEG_BLKS, 256>>>(ei);

    // layer 1 aggregation
    k_aggcsr<false><<<(NN + 7) / 8, 256>>>(b1, batch);

    // layer 2
    k_gemm2<<<(NN + 63) / 64, 256>>>(da, W2, dh);
    k_aggcsr<true><<<(NN + 7) / 8, 256>>>(b2, batch);

    // head
    k_head<<<1, NG>>>(Wfc, bfc, out);
}

// round 7
// speedup vs baseline: 3.3150x; 1.0084x over previous
#include <cuda_runtime.h>

#define NN 100000
#define NE 1600000
#define DIN 128
#define HID 64
#define NG 512
#define NC 10

#define GEMM1_BLKS ((NN + 63) / 64)          // 1563
#define DEG4_BLKS  ((NE / 4 + 255) / 256)    // 1563
#define GCNT4_BLKS ((NN / 4 + 255) / 256)    // 98
#define SCAN_BLKS  ((NN + 1023) / 1024)      // 98

// ---------------- scratch (device globals; no allocation allowed) ----------
__device__ __align__(16) float g_h[NN * HID];
__device__ __align__(16) float g_pool[NG * HID];
__device__ float g_dinv[NN];
__device__ int   g_degi[NN];
__device__ int   g_ptr[NN + 1];
__device__ int   g_pos[NN];
__device__ int   g_gcnt[NG];
__device__ int   g_bsum[SCAN_BLKS];
__device__ int   g_boff[SCAN_BLKS];
__device__ __align__(16) int2 g_edge[NE];    // {src, float_bits(coef)}

// ---------------- GEMM body (layer-1 path) ---------------------------------
template <int K, int LDX>
__device__ __forceinline__ void gemm_body(const float* __restrict__ X,
                                          const float* __restrict__ W,
                                          float* __restrict__ Y, int blk) {
    const int STRIDE = 68;
    __shared__ __align__(16) float xs_t[32 * STRIDE];
    __shared__ __align__(16) float Ws[32 * 64];
    int t = threadIdx.x;
    int i = t >> 4, j = t & 15;
    int node0 = blk * 64;
    float acc[4][4];
#pragma unroll
    for (int r = 0; r < 4; r++)
#pragma unroll
        for (int c = 0; c < 4; c++) acc[r][c] = 0.f;

    for (int k0 = 0; k0 < K; k0 += 32) {
#pragma unroll
        for (int q = 0; q < 2; q++) {
            int idx4 = t + q * 256;
            int row = idx4 >> 3, c4 = idx4 & 7;
            int node = node0 + row;
            if (node >= NN) node = NN - 1;
            float4 v = *(const float4*)&X[(size_t)node * LDX + k0 + c4 * 4];
            xs_t[(c4 * 4 + 0) * STRIDE + row] = v.x;
            xs_t[(c4 * 4 + 1) * STRIDE + row] = v.y;
            xs_t[(c4 * 4 + 2) * STRIDE + row] = v.z;
            xs_t[(c4 * 4 + 3) * STRIDE + row] = v.w;
        }
#pragma unroll
        for (int q = 0; q < 2; q++) {
            int idx4 = t + q * 256;
            int kk = idx4 >> 4, c = idx4 & 15;
            ((float4*)Ws)[kk * 16 + c] = ((const float4*)W)[(k0 + kk) * 16 + c];
        }
        __syncthreads();
#pragma unroll
        for (int kk = 0; kk < 32; kk++) {
            float4 a = *(const float4*)&xs_t[kk * STRIDE + i * 4];
            float4 b = ((const float4*)Ws)[kk * 16 + j];
            acc[0][0] += a.x * b.x; acc[0][1] += a.x * b.y; acc[0][2] += a.x * b.z; acc[0][3] += a.x * b.w;
            acc[1][0] += a.y * b.x; acc[1][1] += a.y * b.y; acc[1][2] += a.y * b.z; acc[1][3] += a.y * b.w;
            acc[2][0] += a.z * b.x; acc[2][1] += a.z * b.y; acc[2][2] += a.z * b.z; acc[2][3] += a.z * b.w;
            acc[3][0] += a.w * b.x; acc[3][1] += a.w * b.y; acc[3][2] += a.w * b.z; acc[3][3] += a.w * b.w;
        }
        __syncthreads();
    }
#pragma unroll
    for (int r = 0; r < 4; r++) {
        int node = node0 + i * 4 + r;
        if (node < NN) {
            float4 v = make_float4(acc[r][0], acc[r][1], acc[r][2], acc[r][3]);
            *(float4*)&Y[(size_t)node * HID + j * 4] = v;
        }
    }
}

// ---------------- fused front: gemm1 | degree histogram | graph histogram --
__global__ void k_front(const float* __restrict__ x, const float* __restrict__ W1,
                        const int* __restrict__ ei, const int* __restrict__ batch,
                        float* __restrict__ Y) {
    int b = blockIdx.x;
    if (b < GEMM1_BLKS) {
        gemm_body<DIN, DIN>(x, W1, Y, b);
    } else if (b < GEMM1_BLKS + DEG4_BLKS) {
        int q = (b - GEMM1_BLKS) * 256 + threadIdx.x;
        if (q < NE / 4) {
            int4 d4 = __ldg((const int4*)(ei + NE) + q);
            atomicAdd(&g_degi[d4.x], 1);
            atomicAdd(&g_degi[d4.y], 1);
            atomicAdd(&g_degi[d4.z], 1);
            atomicAdd(&g_degi[d4.w], 1);
        }
    } else {
        int q = (b - GEMM1_BLKS - DEG4_BLKS) * 256 + threadIdx.x;
        if (q < NN / 4) {
            int4 b4 = __ldg((const int4*)batch + q);
            atomicAdd(&g_gcnt[b4.x], 1);
            atomicAdd(&g_gcnt[b4.y], 1);
            atomicAdd(&g_gcnt[b4.z], 1);
            atomicAdd(&g_gcnt[b4.w], 1);
        }
    }
}

// ---------------- 3-phase parallel scan ------------------------------------
__global__ void k_scan1() {
    __shared__ int wsum[32];
    int b = blockIdx.x, t = threadIdx.x;
    int idx = b * 1024 + t;
    int d = (idx < NN) ? g_degi[idx] : 0;
    int v = d;
#pragma unroll
    for (int o = 16; o > 0; o >>= 1) v += __shfl_down_sync(0xffffffffu, v, o);
    if ((t & 31) == 0) wsum[t >> 5] = v;
    __syncthreads();
    if (t < 32) {
        int s = wsum[t];
#pragma unroll
        for (int o = 16; o > 0; o >>= 1) s += __shfl_down_sync(0xffffffffu, s, o);
        if (t == 0) g_bsum[b] = s;
    }
}

__global__ void k_scan2() {
    __shared__ int s[SCAN_BLKS];
    int t = threadIdx.x;
    if (t < SCAN_BLKS) s[t] = g_bsum[t];
    __syncthreads();
    if (t == 0) {
        int run = 0;
        for (int i = 0; i < SCAN_BLKS; i++) { int v = s[i]; s[i] = run; run += v; }
    }
    __syncthreads();
    if (t < SCAN_BLKS) g_boff[t] = s[t];
}

__global__ void k_scan3() {
    __shared__ int sd[1024];
    int b = blockIdx.x, t = threadIdx.x;
    int idx = b * 1024 + t;
    int d = (idx < NN) ? g_degi[idx] : 0;
    sd[t] = d;
    __syncthreads();
    for (int off = 1; off < 1024; off <<= 1) {
        int v = (t >= off) ? sd[t - off] : 0;
        __syncthreads();
        sd[t] += v;
        __syncthreads();
    }
    if (idx < NN) {
        int excl = sd[t] - d + g_boff[b];
        g_ptr[idx] = excl;
        g_pos[idx] = excl;
        g_dinv[idx] = rsqrtf((float)d + 1.0f);
    }
    if (b == SCAN_BLKS - 1 && t == 0) g_ptr[NN] = NE;
}

__global__ void k_scatter(const int* __restrict__ ei) {
    int e = blockIdx.x * blockDim.x + threadIdx.x;
    if (e >= NE) return;
    int src = __ldg(&ei[e]);
    int dst = __ldg(&ei[NE + e]);
    int p = atomicAdd(&g_pos[dst], 1);
    float cf = __ldg(&g_dinv[src]) * __ldg(&g_dinv[dst]);
    g_edge[p] = make_int2(src, __float_as_int(cf));
}

// ---------------- node aggregation core (warp-collective) ------------------
// Returns relu( sum h[src]*coef + h[node]*dinv^2 + bias ) in sub==0 lanes.
__device__ __forceinline__ float4 agg_node(int node, int j, int sub,
                                           const float* __restrict__ bias) {
    int start = __ldg(&g_ptr[node]);
    int end   = __ldg(&g_ptr[node + 1]);
    const float4* h4 = (const float4*)g_h;
    float4 a0 = make_float4(0.f, 0.f, 0.f, 0.f);
    float4 a1 = make_float4(0.f, 0.f, 0.f, 0.f);
    int p = start + sub;
    for (; p + 2 < end; p += 4) {
        int2 e0 = __ldg(&g_edge[p]);
        int2 e1 = __ldg(&g_edge[p + 2]);
        float c0 = __int_as_float(e0.y);
        float c1 = __int_as_float(e1.y);
        float4 v0 = __ldg(h4 + (size_t)e0.x * 16 + j);
        float4 v1 = __ldg(h4 + (size_t)e1.x * 16 + j);
        a0.x += v0.x * c0; a0.y += v0.y * c0; a0.z += v0.z * c0; a0.w += v0.w * c0;
        a1.x += v1.x * c1; a1.y += v1.y * c1; a1.z += v1.z * c1; a1.w += v1.w * c1;
    }
    if (p < end) {
        int2 e0 = __ldg(&g_edge[p]);
        float c0 = __int_as_float(e0.y);
        float4 v0 = __ldg(h4 + (size_t)e0.x * 16 + j);
        a0.x += v0.x * c0; a0.y += v0.y * c0; a0.z += v0.z * c0; a0.w += v0.w * c0;
    }
    a0.x += a1.x; a0.y += a1.y; a0.z += a1.z; a0.w += a1.w;
    a0.x += __shfl_down_sync(0xffffffffu, a0.x, 16);
    a0.y += __shfl_down_sync(0xffffffffu, a0.y, 16);
    a0.z += __shfl_down_sync(0xffffffffu, a0.z, 16);
    a0.w += __shfl_down_sync(0xffffffffu, a0.w, 16);
    float4 r = make_float4(0.f, 0.f, 0.f, 0.f);
    if (sub == 0) {
        float dn = __ldg(&g_dinv[node]);
        float c = dn * dn;
        float4 h = __ldg((const float4*)g_h + (size_t)node * 16 + j);
        float4 b = __ldg((const float4*)bias + j);
        r.x = fmaxf(a0.x + h.x * c + b.x, 0.f);
        r.y = fmaxf(a0.y + h.y * c + b.y, 0.f);
        r.z = fmaxf(a0.z + h.z * c + b.z, 0.f);
        r.w = fmaxf(a0.w + h.w * c + b.w, 0.f);
    }
    return r;
}

// ---------------- fused agg1 + gemm2: block = 64 nodes ---------------------
// Aggregate (relu'd) rows directly into transposed smem, then GEMM with W2.
__global__ void k_mid(const float* __restrict__ bias, const float* __restrict__ W2,
                      float* __restrict__ Y) {
    const int STRIDE = 68;
    __shared__ __align__(16) float as_t[64 * STRIDE];   // [k][node]
    __shared__ __align__(16) float Ws[64 * 64];         // [k][col]
    int t = threadIdx.x;
    int warp = t >> 5, lane = t & 31;
    int j = lane & 15, sub = lane >> 4;
    int node0 = blockIdx.x * 64;

    // preload all of W2 (64x64) — 4 float4 per thread
#pragma unroll
    for (int q = 0; q < 4; q++) {
        int idx4 = t + q * 256;
        ((float4*)Ws)[idx4] = ((const float4*)W2)[idx4];
    }

    // aggregation: each warp owns 8 node rows
#pragma unroll 1
    for (int s = 0; s < 8; s++) {
        int row = warp * 8 + s;
        int node = node0 + row;
        float4 r = make_float4(0.f, 0.f, 0.f, 0.f);
        if (node < NN) r = agg_node(node, j, sub, bias);
        if (sub == 0) {
            as_t[(4 * j + 0) * STRIDE + row] = r.x;
            as_t[(4 * j + 1) * STRIDE + row] = r.y;
            as_t[(4 * j + 2) * STRIDE + row] = r.z;
            as_t[(4 * j + 3) * STRIDE + row] = r.w;
        }
    }
    __syncthreads();

    // GEMM: 64x64 tile @ W2(64x64)
    int i = t >> 4, jj = t & 15;
    float acc[4][4];
#pragma unroll
    for (int r = 0; r < 4; r++)
#pragma unroll
        for (int c = 0; c < 4; c++) acc[r][c] = 0.f;
#pragma unroll
    for (int kk = 0; kk < 64; kk++) {
        float4 a = *(const float4*)&as_t[kk * STRIDE + i * 4];
        float4 b = ((const float4*)Ws)[kk * 16 + jj];
        acc[0][0] += a.x * b.x; acc[0][1] += a.x * b.y; acc[0][2] += a.x * b.z; acc[0][3] += a.x * b.w;
        acc[1][0] += a.y * b.x; acc[1][1] += a.y * b.y; acc[1][2] += a.y * b.z; acc[1][3] += a.y * b.w;
        acc[2][0] += a.z * b.x; acc[2][1] += a.z * b.y; acc[2][2] += a.z * b.z; acc[2][3] += a.z * b.w;
        acc[3][0] += a.w * b.x; acc[3][1] += a.w * b.y; acc[3][2] += a.w * b.z; acc[3][3] += a.w * b.w;
    }
#pragma unroll
    for (int r = 0; r < 4; r++) {
        int node = node0 + i * 4 + r;
        if (node < NN) {
            float4 v = make_float4(acc[r][0], acc[r][1], acc[r][2], acc[r][3]);
            *(float4*)&Y[(size_t)node * HID + jj * 4] = v;
        }
    }
}

// ---------------- layer-2 aggregation + fused pool -------------------------
__global__ void k_aggpool(const float* __restrict__ bias,
                          const int* __restrict__ batch) {
    int warp = threadIdx.x >> 5, lane = threadIdx.x & 31;
    int j = lane & 15, sub = lane >> 4;
    int node = blockIdx.x * 8 + warp;
    if (node >= NN) return;
    float4 r = agg_node(node, j, sub, bias);
    if (sub == 0) {
        int g = __ldg(&batch[node]);
        float4* p4 = (float4*)g_pool + (size_t)g * 16 + j;
        asm volatile("red.global.add.v4.f32 [%0], {%1, %2, %3, %4};"
                     :: "l"(p4), "f"(r.x), "f"(r.y), "f"(r.z), "f"(r.w)
                     : "memory");
    }
}

// ---------------- head -----------------------------------------------------
__global__ void k_head(const float* __restrict__ Wfc, const float* __restrict__ bfc,
                       float* __restrict__ out) {
    __shared__ float Wf[HID * NC];
    __shared__ float bf[NC];
    for (int i = threadIdx.x; i < HID * NC; i += blockDim.x) Wf[i] = Wfc[i];
    if (threadIdx.x < NC) bf[threadIdx.x] = bfc[threadIdx.x];
    __syncthreads();
    int g = blockIdx.x * blockDim.x + threadIdx.x;
    if (g >= NG) return;
    float inv = 1.0f / fmaxf((float)g_gcnt[g], 1.0f);
    float l[NC];
#pragma unroll
    for (int j = 0; j < NC; j++) l[j] = bf[j];
    for (int k = 0; k < HID; k++) {
        float pv = g_pool[g * HID + k] * inv;
#pragma unroll
        for (int j = 0; j < NC; j++) l[j] += pv * Wf[k * NC + j];
    }
    float m = l[0];
#pragma unroll
    for (int j = 1; j < NC; j++) m = fmaxf(m, l[j]);
    float s = 0.f;
#pragma unroll
    for (int j = 0; j < NC; j++) s += expf(l[j] - m);
    float lse = m + logf(s);
#pragma unroll
    for (int j = 0; j < NC; j++) out[g * NC + j] = l[j] - lse;
}

// ---------------------------------------------------------------------------
extern "C" void kernel_launch(void* const* d_in, const int* in_sizes, int n_in,
                              void* d_out, int out_size) {
    const float* x     = (const float*)d_in[0];
    const int*   ei    = (const int*)d_in[1];
    const int*   batch = (const int*)d_in[2];
    const float* W1    = (const float*)d_in[3];
    const float* b1    = (const float*)d_in[4];
    const float* W2    = (const float*)d_in[5];
    const float* b2    = (const float*)d_in[6];
    const float* Wfc   = (const float*)d_in[7];
    const float* bfc   = (const float*)d_in[8];
    float* out = (float*)d_out;

    // Resolve REAL device addresses (host shadow symbols are a silent ATS trap).
    void *p_degi, *p_gcnt, *p_pool, *p_h;
    cudaGetSymbolAddress(&p_degi, g_degi);
    cudaGetSymbolAddress(&p_gcnt, g_gcnt);
    cudaGetSymbolAddress(&p_pool, g_pool);
    cudaGetSymbolAddress(&p_h,    g_h);
    float* dh = (float*)p_h;

    cudaMemsetAsync(p_degi, 0, NN * sizeof(int));
    cudaMemsetAsync(p_gcnt, 0, NG * sizeof(int));
    cudaMemsetAsync(p_pool, 0, NG * HID * sizeof(float));

    // fused: gemm1 + degree histogram + graph histogram
    k_front<<<GEMM1_BLKS + DEG4_BLKS + GCNT4_BLKS, 256>>>(x, W1, ei, batch, dh);

    // CSR pointers + packed edge scatter
    k_scan1<<<SCAN_BLKS, 1024>>>();
    k_scan2<<<1, 128>>>();
    k_scan3<<<SCAN_BLKS, 1024>>>();
    k_scatter<<<(NE + 255) / 256, 256>>>(ei);

    // fused agg1 + gemm2 (writes g_h)
    k_mid<<<(NN + 63) / 64, 256>>>(b1, W2, dh);

    // layer-2 aggregation + fused pool
    k_aggpool<<<(NN + 7) / 8, 256>>>(b2, batch);

    // head
    k_head<<<1, NG>>>(Wfc, bfc, out);
}

// round 8
// speedup vs baseline: 3.4369x; 1.0368x over previous
#include <cuda_runtime.h>
#include <cuda_fp16.h>

#define NN 100000
#define NE 1600000
#define DIN 128
#define HID 64
#define NG 512
#define NC 10

#define GEMM1_BLKS ((NN + 63) / 64)          // 1563
#define DEG4_BLKS  ((NE / 4 + 255) / 256)    // 1563
#define GCNT4_BLKS ((NN / 4 + 255) / 256)    // 98
#define SCAN_BLKS  ((NN + 1023) / 1024)      // 98

// ---------------- scratch (device globals; no allocation allowed) ----------
// Feature tables stored fp16 (fp32 accumulation everywhere). Row = 64 halves
// = 128 B = 16 uint2.
__device__ __align__(16) __half g_h[NN * HID];    // layer-1 features
__device__ __align__(16) __half g_h2[NN * HID];   // layer-2 features (k_mid out)
__device__ __align__(16) float g_pool[NG * HID];
__device__ float g_dinv[NN];
__device__ int   g_degi[NN];
__device__ int   g_ptr[NN + 1];
__device__ int   g_pos[NN];
__device__ int   g_gcnt[NG];
__device__ int   g_bsum[SCAN_BLKS];
__device__ int   g_boff[SCAN_BLKS];
__device__ __align__(16) int2 g_edge[NE];    // {src, float_bits(coef)}

union HPack { uint2 u; __half2 h[2]; };

// ---------------- GEMM body (layer-1): fp32 in, fp16 out -------------------
template <int K, int LDX>
__device__ __forceinline__ void gemm_body(const float* __restrict__ X,
                                          const float* __restrict__ W,
                                          __half* __restrict__ Y, int blk) {
    const int STRIDE = 68;
    __shared__ __align__(16) float xs_t[32 * STRIDE];
    __shared__ __align__(16) float Ws[32 * 64];
    int t = threadIdx.x;
    int i = t >> 4, j = t & 15;
    int node0 = blk * 64;
    float acc[4][4];
#pragma unroll
    for (int r = 0; r < 4; r++)
#pragma unroll
        for (int c = 0; c < 4; c++) acc[r][c] = 0.f;

    for (int k0 = 0; k0 < K; k0 += 32) {
#pragma unroll
        for (int q = 0; q < 2; q++) {
            int idx4 = t + q * 256;
            int row = idx4 >> 3, c4 = idx4 & 7;
            int node = node0 + row;
            if (node >= NN) node = NN - 1;
            float4 v = *(const float4*)&X[(size_t)node * LDX + k0 + c4 * 4];
            xs_t[(c4 * 4 + 0) * STRIDE + row] = v.x;
            xs_t[(c4 * 4 + 1) * STRIDE + row] = v.y;
            xs_t[(c4 * 4 + 2) * STRIDE + row] = v.z;
            xs_t[(c4 * 4 + 3) * STRIDE + row] = v.w;
        }
#pragma unroll
        for (int q = 0; q < 2; q++) {
            int idx4 = t + q * 256;
            int kk = idx4 >> 4, c = idx4 & 15;
            ((float4*)Ws)[kk * 16 + c] = ((const float4*)W)[(k0 + kk) * 16 + c];
        }
        __syncthreads();
#pragma unroll
        for (int kk = 0; kk < 32; kk++) {
            float4 a = *(const float4*)&xs_t[kk * STRIDE + i * 4];
            float4 b = ((const float4*)Ws)[kk * 16 + j];
            acc[0][0] += a.x * b.x; acc[0][1] += a.x * b.y; acc[0][2] += a.x * b.z; acc[0][3] += a.x * b.w;
            acc[1][0] += a.y * b.x; acc[1][1] += a.y * b.y; acc[1][2] += a.y * b.z; acc[1][3] += a.y * b.w;
            acc[2][0] += a.z * b.x; acc[2][1] += a.z * b.y; acc[2][2] += a.z * b.z; acc[2][3] += a.z * b.w;
            acc[3][0] += a.w * b.x; acc[3][1] += a.w * b.y; acc[3][2] += a.w * b.z; acc[3][3] += a.w * b.w;
        }
        __syncthreads();
    }
#pragma unroll
    for (int r = 0; r < 4; r++) {
        int node = node0 + i * 4 + r;
        if (node < NN) {
            HPack pk;
            pk.h[0] = __floats2half2_rn(acc[r][0], acc[r][1]);
            pk.h[1] = __floats2half2_rn(acc[r][2], acc[r][3]);
            ((uint2*)Y)[(size_t)node * 16 + j] = pk.u;
        }
    }
}

// ---------------- fused front: gemm1 | degree histogram | graph histogram --
__global__ void k_front(const float* __restrict__ x, const float* __restrict__ W1,
                        const int* __restrict__ ei, const int* __restrict__ batch,
                        __half* __restrict__ Y) {
    int b = blockIdx.x;
    if (b < GEMM1_BLKS) {
        gemm_body<DIN, DIN>(x, W1, Y, b);
    } else if (b < GEMM1_BLKS + DEG4_BLKS) {
        int q = (b - GEMM1_BLKS) * 256 + threadIdx.x;
        if (q < NE / 4) {
            int4 d4 = __ldg((const int4*)(ei + NE) + q);
            atomicAdd(&g_degi[d4.x], 1);
            atomicAdd(&g_degi[d4.y], 1);
            atomicAdd(&g_degi[d4.z], 1);
            atomicAdd(&g_degi[d4.w], 1);
        }
    } else {
        int q = (b - GEMM1_BLKS - DEG4_BLKS) * 256 + threadIdx.x;
        if (q < NN / 4) {
            int4 b4 = __ldg((const int4*)batch + q);
            atomicAdd(&g_gcnt[b4.x], 1);
            atomicAdd(&g_gcnt[b4.y], 1);
            atomicAdd(&g_gcnt[b4.z], 1);
            atomicAdd(&g_gcnt[b4.w], 1);
        }
    }
}

// ---------------- 3-phase parallel scan ------------------------------------
__global__ void k_scan1() {
    __shared__ int wsum[32];
    int b = blockIdx.x, t = threadIdx.x;
    int idx = b * 1024 + t;
    int d = (idx < NN) ? g_degi[idx] : 0;
    int v = d;
#pragma unroll
    for (int o = 16; o > 0; o >>= 1) v += __shfl_down_sync(0xffffffffu, v, o);
    if ((t & 31) == 0) wsum[t >> 5] = v;
    __syncthreads();
    if (t < 32) {
        int s = wsum[t];
#pragma unroll
        for (int o = 16; o > 0; o >>= 1) s += __shfl_down_sync(0xffffffffu, s, o);
        if (t == 0) g_bsum[b] = s;
    }
}

__global__ void k_scan2() {
    __shared__ int s[SCAN_BLKS];
    int t = threadIdx.x;
    if (t < SCAN_BLKS) s[t] = g_bsum[t];
    __syncthreads();
    if (t == 0) {
        int run = 0;
        for (int i = 0; i < SCAN_BLKS; i++) { int v = s[i]; s[i] = run; run += v; }
    }
    __syncthreads();
    if (t < SCAN_BLKS) g_boff[t] = s[t];
}

__global__ void k_scan3() {
    __shared__ int sd[1024];
    int b = blockIdx.x, t = threadIdx.x;
    int idx = b * 1024 + t;
    int d = (idx < NN) ? g_degi[idx] : 0;
    sd[t] = d;
    __syncthreads();
    for (int off = 1; off < 1024; off <<= 1) {
        int v = (t >= off) ? sd[t - off] : 0;
        __syncthreads();
        sd[t] += v;
        __syncthreads();
    }
    if (idx < NN) {
        int excl = sd[t] - d + g_boff[b];
        g_ptr[idx] = excl;
        g_pos[idx] = excl;
        g_dinv[idx] = rsqrtf((float)d + 1.0f);
    }
    if (b == SCAN_BLKS - 1 && t == 0) g_ptr[NN] = NE;
}

__global__ void k_scatter(const int* __restrict__ ei) {
    int e = blockIdx.x * blockDim.x + threadIdx.x;
    if (e >= NE) return;
    int src = __ldg(&ei[e]);
    int dst = __ldg(&ei[NE + e]);
    int p = atomicAdd(&g_pos[dst], 1);
    float cf = __ldg(&g_dinv[src]) * __ldg(&g_dinv[dst]);
    g_edge[p] = make_int2(src, __float_as_int(cf));
}

// ---------------- node aggregation core (warp-collective, fp16 table) ------
// Returns relu( sum h[src]*coef + h[node]*dinv^2 + bias ) in sub==0 lanes.
// H: fp16 feature table, row = 16 uint2. Lane j covers features 4j..4j+3.
__device__ __forceinline__ float4 agg_node(const __half* __restrict__ H,
                                           int node, int j, int sub,
                                           const float* __restrict__ bias) {
    int start = __ldg(&g_ptr[node]);
    int end   = __ldg(&g_ptr[node + 1]);
    const uint2* h2 = (const uint2*)H;
    float4 a0 = make_float4(0.f, 0.f, 0.f, 0.f);
    float4 a1 = make_float4(0.f, 0.f, 0.f, 0.f);
    int p = start + sub;
    for (; p + 2 < end; p += 4) {
        int2 e0 = __ldg(&g_edge[p]);
        int2 e1 = __ldg(&g_edge[p + 2]);
        float c0 = __int_as_float(e0.y);
        float c1 = __int_as_float(e1.y);
        HPack v0, v1;
        v0.u = __ldg(h2 + (size_t)e0.x * 16 + j);
        v1.u = __ldg(h2 + (size_t)e1.x * 16 + j);
        float2 f0a = __half22float2(v0.h[0]), f0b = __half22float2(v0.h[1]);
        float2 f1a = __half22float2(v1.h[0]), f1b = __half22float2(v1.h[1]);
        a0.x += f0a.x * c0; a0.y += f0a.y * c0; a0.z += f0b.x * c0; a0.w += f0b.y * c0;
        a1.x += f1a.x * c1; a1.y += f1a.y * c1; a1.z += f1b.x * c1; a1.w += f1b.y * c1;
    }
    if (p < end) {
        int2 e0 = __ldg(&g_edge[p]);
        float c0 = __int_as_float(e0.y);
        HPack v0;
        v0.u = __ldg(h2 + (size_t)e0.x * 16 + j);
        float2 f0a = __half22float2(v0.h[0]), f0b = __half22float2(v0.h[1]);
        a0.x += f0a.x * c0; a0.y += f0a.y * c0; a0.z += f0b.x * c0; a0.w += f0b.y * c0;
    }
    a0.x += a1.x; a0.y += a1.y; a0.z += a1.z; a0.w += a1.w;
    a0.x += __shfl_down_sync(0xffffffffu, a0.x, 16);
    a0.y += __shfl_down_sync(0xffffffffu, a0.y, 16);
    a0.z += __shfl_down_sync(0xffffffffu, a0.z, 16);
    a0.w += __shfl_down_sync(0xffffffffu, a0.w, 16);
    float4 r = make_float4(0.f, 0.f, 0.f, 0.f);
    if (sub == 0) {
        float dn = __ldg(&g_dinv[node]);
        float c = dn * dn;
        HPack hs;
        hs.u = __ldg(h2 + (size_t)node * 16 + j);
        float2 ha = __half22float2(hs.h[0]), hb = __half22float2(hs.h[1]);
        float4 b = __ldg((const float4*)bias + j);
        r.x = fmaxf(a0.x + ha.x * c + b.x, 0.f);
        r.y = fmaxf(a0.y + ha.y * c + b.y, 0.f);
        r.z = fmaxf(a0.z + hb.x * c + b.z, 0.f);
        r.w = fmaxf(a0.w + hb.y * c + b.w, 0.f);
    }
    return r;
}

// ---------------- fused agg1 + gemm2: reads g_h, writes g_h2 ---------------
__global__ void k_mid(const float* __restrict__ bias, const float* __restrict__ W2,
                      __half* __restrict__ Y) {
    const int STRIDE = 68;
    __shared__ __align__(16) float as_t[64 * STRIDE];   // [k][node]
    __shared__ __align__(16) float Ws[64 * 64];         // [k][col]
    int t = threadIdx.x;
    int warp = t >> 5, lane = t & 31;
    int j = lane & 15, sub = lane >> 4;
    int node0 = blockIdx.x * 64;

#pragma unroll
    for (int q = 0; q < 4; q++) {
        int idx4 = t + q * 256;
        ((float4*)Ws)[idx4] = ((const float4*)W2)[idx4];
    }

#pragma unroll 1
    for (int s = 0; s < 8; s++) {
        int row = warp * 8 + s;
        int node = node0 + row;
        float4 r = make_float4(0.f, 0.f, 0.f, 0.f);
        if (node < NN) r = agg_node(g_h, node, j, sub, bias);
        if (sub == 0) {
            as_t[(4 * j + 0) * STRIDE + row] = r.x;
            as_t[(4 * j + 1) * STRIDE + row] = r.y;
            as_t[(4 * j + 2) * STRIDE + row] = r.z;
            as_t[(4 * j + 3) * STRIDE + row] = r.w;
        }
    }
    __syncthreads();

    int i = t >> 4, jj = t & 15;
    float acc[4][4];
#pragma unroll
    for (int r = 0; r < 4; r++)
#pragma unroll
        for (int c = 0; c < 4; c++) acc[r][c] = 0.f;
#pragma unroll
    for (int kk = 0; kk < 64; kk++) {
        float4 a = *(const float4*)&as_t[kk * STRIDE + i * 4];
        float4 b = ((const float4*)Ws)[kk * 16 + jj];
        acc[0][0] += a.x * b.x; acc[0][1] += a.x * b.y; acc[0][2] += a.x * b.z; acc[0][3] += a.x * b.w;
        acc[1][0] += a.y * b.x; acc[1][1] += a.y * b.y; acc[1][2] += a.y * b.z; acc[1][3] += a.y * b.w;
        acc[2][0] += a.z * b.x; acc[2][1] += a.z * b.y; acc[2][2] += a.z * b.z; acc[2][3] += a.z * b.w;
        acc[3][0] += a.w * b.x; acc[3][1] += a.w * b.y; acc[3][2] += a.w * b.z; acc[3][3] += a.w * b.w;
    }
#pragma unroll
    for (int r = 0; r < 4; r++) {
        int node = node0 + i * 4 + r;
        if (node < NN) {
            HPack pk;
            pk.h[0] = __floats2half2_rn(acc[r][0], acc[r][1]);
            pk.h[1] = __floats2half2_rn(acc[r][2], acc[r][3]);
            ((uint2*)Y)[(size_t)node * 16 + jj] = pk.u;
        }
    }
}

// ---------------- layer-2 aggregation + fused pool (reads g_h2) ------------
__global__ void k_aggpool(const float* __restrict__ bias,
                          const int* __restrict__ batch) {
    int warp = threadIdx.x >> 5, lane = threadIdx.x & 31;
    int j = lane & 15, sub = lane >> 4;
    int node = blockIdx.x * 8 + warp;
    if (node >= NN) return;
    float4 r = agg_node(g_h2, node, j, sub, bias);
    if (sub == 0) {
        int g = __ldg(&batch[node]);
        float4* p4 = (float4*)g_pool + (size_t)g * 16 + j;
        asm volatile("red.global.add.v4.f32 [%0], {%1, %2, %3, %4};"
                     :: "l"(p4), "f"(r.x), "f"(r.y), "f"(r.z), "f"(r.w)
                     : "memory");
    }
}

// ---------------- head -----------------------------------------------------
__global__ void k_head(const float* __restrict__ Wfc, const float* __restrict__ bfc,
                       float* __restrict__ out) {
    __shared__ float Wf[HID * NC];
    __shared__ float bf[NC];
    for (int i = threadIdx.x; i < HID * NC; i += blockDim.x) Wf[i] = Wfc[i];
    if (threadIdx.x < NC) bf[threadIdx.x] = bfc[threadIdx.x];
    __syncthreads();
    int g = blockIdx.x * blockDim.x + threadIdx.x;
    if (g >= NG) return;
    float inv = 1.0f / fmaxf((float)g_gcnt[g], 1.0f);
    float l[NC];
#pragma unroll
    for (int j = 0; j < NC; j++) l[j] = bf[j];
    for (int k = 0; k < HID; k++) {
        float pv = g_pool[g * HID + k] * inv;
#pragma unroll
        for (int j = 0; j < NC; j++) l[j] += pv * Wf[k * NC + j];
    }
    float m = l[0];
#pragma unroll
    for (int j = 1; j < NC; j++) m = fmaxf(m, l[j]);
    float s = 0.f;
#pragma unroll
    for (int j = 0; j < NC; j++) s += expf(l[j] - m);
    float lse = m + logf(s);
#pragma unroll
    for (int j = 0; j < NC; j++) out[g * NC + j] = l[j] - lse;
}

// ---------------------------------------------------------------------------
extern "C" void kernel_launch(void* const* d_in, const int* in_sizes, int n_in,
                              void* d_out, int out_size) {
    const float* x     = (const float*)d_in[0];
    const int*   ei    = (const int*)d_in[1];
    const int*   batch = (const int*)d_in[2];
    const float* W1    = (const float*)d_in[3];
    const float* b1    = (const float*)d_in[4];
    const float* W2    = (const float*)d_in[5];
    const float* b2    = (const float*)d_in[6];
    const float* Wfc   = (const float*)d_in[7];
    const float* bfc   = (const float*)d_in[8];
    float* out = (float*)d_out;

    // Resolve REAL device addresses (host shadow symbols are a silent ATS trap).
    void *p_degi, *p_gcnt, *p_pool, *p_h, *p_h2;
    cudaGetSymbolAddress(&p_degi, g_degi);
    cudaGetSymbolAddress(&p_gcnt, g_gcnt);
    cudaGetSymbolAddress(&p_pool, g_pool);
    cudaGetSymbolAddress(&p_h,    g_h);
    cudaGetSymbolAddress(&p_h2,   g_h2);
    __half* dh  = (__half*)p_h;
    __half* dh2 = (__half*)p_h2;

    cudaMemsetAsync(p_degi, 0, NN * sizeof(int));
    cudaMemsetAsync(p_gcnt, 0, NG * sizeof(int));
    cudaMemsetAsync(p_pool, 0, NG * HID * sizeof(float));

    // fused: gemm1 + degree histogram + graph histogram
    k_front<<<GEMM1_BLKS + DEG4_BLKS + GCNT4_BLKS, 256>>>(x, W1, ei, batch, dh);

    // CSR pointers + packed edge scatter
    k_scan1<<<SCAN_BLKS, 1024>>>();
    k_scan2<<<1, 128>>>();
    k_scan3<<<SCAN_BLKS, 1024>>>();
    k_scatter<<<(NE + 255) / 256, 256>>>(ei);

    // fused agg1 + gemm2: reads g_h, writes g_h2 (separate buffer — no race)
    k_mid<<<(NN + 63) / 64, 256>>>(b1, W2, dh2);

    // layer-2 aggregation + fused pool (reads g_h2)
    k_aggpool<<<(NN + 7) / 8, 256>>>(b2, batch);

    // head
    k_head<<<1, NG>>>(Wfc, bfc, out);
}

// round 9
// speedup vs baseline: 3.8339x; 1.1155x over previous
#include <cuda_runtime.h>
#include <cuda_fp16.h>

#define NN 100000
#define NE 1600000
#define DIN 128
#define HID 64
#define NG 512
#define NC 10

#define GEMM1_BLKS ((NN + 63) / 64)          // 1563
#define DEG4_BLKS  ((NE / 4 + 255) / 256)    // 1563
#define GCNT4_BLKS ((NN / 4 + 255) / 256)    // 98
#define SCAN_BLKS  ((NN + 1023) / 1024)      // 98

// ---------------- scratch (device globals; no allocation allowed) ----------
__device__ __align__(16) __half g_h[NN * HID];    // layer-1 features
__device__ __align__(16) __half g_h2[NN * HID];   // layer-2 features
__device__ __align__(16) __half g_W1t[HID * DIN]; // W1^T fp16 [n][k]
__device__ __align__(16) __half g_W2t[HID * HID]; // W2^T fp16 [n][k]
__device__ __align__(16) float g_pool[NG * HID];
__device__ float g_dinv[NN];
__device__ int   g_degi[NN];
__device__ int   g_ptr[NN + 1];
__device__ int   g_pos[NN];
__device__ int   g_gcnt[NG];
__device__ int   g_bsum[SCAN_BLKS];
__device__ int   g_boff[SCAN_BLKS];
__device__ __align__(16) int2 g_edge[NE];    // {src, float_bits(coef)}

union HPack { uint2 u; __half2 h[2]; };

// ---------------- HMMA helper ----------------------------------------------
__device__ __forceinline__ void mma16816(float* c, unsigned a0, unsigned a1,
                                         unsigned a2, unsigned a3,
                                         unsigned b0, unsigned b1) {
    asm volatile(
        "mma.sync.aligned.m16n8k16.row.col.f32.f16.f16.f32 "
        "{%0,%1,%2,%3}, {%4,%5,%6,%7}, {%8,%9}, {%0,%1,%2,%3};"
        : "+f"(c[0]), "+f"(c[1]), "+f"(c[2]), "+f"(c[3])
        : "r"(a0), "r"(a1), "r"(a2), "r"(a3), "r"(b0), "r"(b1));
}

// ---------------- prep: transpose weights to fp16 [n][k] -------------------
__global__ void k_prep(const float* __restrict__ W1, const float* __restrict__ W2) {
    int t = blockIdx.x * 256 + threadIdx.x;
    if (t < DIN * HID) {
        int k = t >> 6, n = t & 63;
        g_W1t[n * DIN + k] = __float2half(W1[t]);
    } else if (t < DIN * HID + HID * HID) {
        int q = t - DIN * HID;
        int k = q >> 6, n = q & 63;
        g_W2t[n * HID + k] = __float2half(W2[q]);
    }
}

// ---------------- gemm1 via HMMA: Y = fp16(X @ W1) -------------------------
// block: 64 nodes x 64 cols, 8 warps; warp w: m-tile (w>>1)*16, n-tile (w&1)*32
__device__ __forceinline__ void gemm1_mma(const float* __restrict__ X,
                                          __half* __restrict__ Y, int blk) {
    const int XS = 136;   // padded halves per row (conflict-free frag loads)
    __shared__ __align__(16) __half Xs[64 * XS];
    __shared__ __align__(16) __half Ws[64 * XS];
    int t = threadIdx.x;
    int node0 = blk * 64;
    // fill Xs: 64x128 fp32 -> fp16
#pragma unroll
    for (int i = 0; i < 8; i++) {
        int idx = t + i * 256;
        int row = idx >> 5, c4 = idx & 31;
        int node = node0 + row;
        if (node >= NN) node = NN - 1;
        float4 v = __ldg((const float4*)&X[(size_t)node * DIN + c4 * 4]);
        HPack pk;
        pk.h[0] = __floats2half2_rn(v.x, v.y);
        pk.h[1] = __floats2half2_rn(v.z, v.w);
        *(uint2*)&Xs[row * XS + c4 * 4] = pk.u;
    }
    // fill Ws from g_W1t [64][128] fp16 (row = n, k contiguous)
#pragma unroll
    for (int i = 0; i < 4; i++) {
        int idx = t + i * 256;
        int row = idx >> 4, c = idx & 15;
        ((float4*)Ws)[row * 17 + c] = ((const float4*)g_W1t)[row * 16 + c];
    }
    __syncthreads();

    int warp = t >> 5, lane = t & 31;
    int g = lane >> 2, tq = lane & 3;
    int mrow = (warp >> 1) * 16, ncol = (warp & 1) * 32;
    float acc[4][4];
#pragma unroll
    for (int j = 0; j < 4; j++)
#pragma unroll
        for (int c = 0; c < 4; c++) acc[j][c] = 0.f;

#pragma unroll
    for (int k0 = 0; k0 < DIN / 16; k0++) {
        int kb = k0 * 16 + 2 * tq;
        unsigned a0 = *(const unsigned*)&Xs[(mrow + g) * XS + kb];
        unsigned a1 = *(const unsigned*)&Xs[(mrow + g + 8) * XS + kb];
        unsigned a2 = *(const unsigned*)&Xs[(mrow + g) * XS + kb + 8];
        unsigned a3 = *(const unsigned*)&Xs[(mrow + g + 8) * XS + kb + 8];
#pragma unroll
        for (int j = 0; j < 4; j++) {
            int n = ncol + j * 8 + g;
            unsigned b0 = *(const unsigned*)&Ws[n * XS + kb];
            unsigned b1 = *(const unsigned*)&Ws[n * XS + kb + 8];
            mma16816(acc[j], a0, a1, a2, a3, b0, b1);
        }
    }
#pragma unroll
    for (int j = 0; j < 4; j++) {
        int col = ncol + j * 8 + 2 * tq;
        int n1 = node0 + mrow + g, n2 = n1 + 8;
        if (n1 < NN) {
            __half2 p = __floats2half2_rn(acc[j][0], acc[j][1]);
            *(__half2*)&Y[(size_t)n1 * HID + col] = p;
        }
        if (n2 < NN) {
            __half2 p = __floats2half2_rn(acc[j][2], acc[j][3]);
            *(__half2*)&Y[(size_t)n2 * HID + col] = p;
        }
    }
}

// ---------------- fused front: gemm1 | degree histogram | graph histogram --
__global__ void k_front(const float* __restrict__ x,
                        const int* __restrict__ ei, const int* __restrict__ batch,
                        __half* __restrict__ Y) {
    int b = blockIdx.x;
    if (b < GEMM1_BLKS) {
        gemm1_mma(x, Y, b);
    } else if (b < GEMM1_BLKS + DEG4_BLKS) {
        int q = (b - GEMM1_BLKS) * 256 + threadIdx.x;
        if (q < NE / 4) {
            int4 d4 = __ldg((const int4*)(ei + NE) + q);
            atomicAdd(&g_degi[d4.x], 1);
            atomicAdd(&g_degi[d4.y], 1);
            atomicAdd(&g_degi[d4.z], 1);
            atomicAdd(&g_degi[d4.w], 1);
        }
    } else {
        int q = (b - GEMM1_BLKS - DEG4_BLKS) * 256 + threadIdx.x;
        if (q < NN / 4) {
            int4 b4 = __ldg((const int4*)batch + q);
            atomicAdd(&g_gcnt[b4.x], 1);
            atomicAdd(&g_gcnt[b4.y], 1);
            atomicAdd(&g_gcnt[b4.z], 1);
            atomicAdd(&g_gcnt[b4.w], 1);
        }
    }
}

// ---------------- 3-phase parallel scan ------------------------------------
__global__ void k_scan1() {
    __shared__ int wsum[32];
    int b = blockIdx.x, t = threadIdx.x;
    int idx = b * 1024 + t;
    int d = (idx < NN) ? g_degi[idx] : 0;
    int v = d;
#pragma unroll
    for (int o = 16; o > 0; o >>= 1) v += __shfl_down_sync(0xffffffffu, v, o);
    if ((t & 31) == 0) wsum[t >> 5] = v;
    __syncthreads();
    if (t < 32) {
        int s = wsum[t];
#pragma unroll
        for (int o = 16; o > 0; o >>= 1) s += __shfl_down_sync(0xffffffffu, s, o);
        if (t == 0) g_bsum[b] = s;
    }
}

__global__ void k_scan2() {
    __shared__ int s[SCAN_BLKS];
    int t = threadIdx.x;
    if (t < SCAN_BLKS) s[t] = g_bsum[t];
    __syncthreads();
    if (t == 0) {
        int run = 0;
        for (int i = 0; i < SCAN_BLKS; i++) { int v = s[i]; s[i] = run; run += v; }
    }
    __syncthreads();
    if (t < SCAN_BLKS) g_boff[t] = s[t];
}

__global__ void k_scan3() {
    __shared__ int sd[1024];
    int b = blockIdx.x, t = threadIdx.x;
    int idx = b * 1024 + t;
    int d = (idx < NN) ? g_degi[idx] : 0;
    sd[t] = d;
    __syncthreads();
    for (int off = 1; off < 1024; off <<= 1) {
        int v = (t >= off) ? sd[t - off] : 0;
        __syncthreads();
        sd[t] += v;
        __syncthreads();
    }
    if (idx < NN) {
        int excl = sd[t] - d + g_boff[b];
        g_ptr[idx] = excl;
        g_pos[idx] = excl;
        g_dinv[idx] = rsqrtf((float)d + 1.0f);
    }
    if (b == SCAN_BLKS - 1 && t == 0) g_ptr[NN] = NE;
}

__global__ void k_scatter(const int* __restrict__ ei) {
    int e = blockIdx.x * blockDim.x + threadIdx.x;
    if (e >= NE) return;
    int src = __ldg(&ei[e]);
    int dst = __ldg(&ei[NE + e]);
    int p = atomicAdd(&g_pos[dst], 1);
    float cf = __ldg(&g_dinv[src]) * __ldg(&g_dinv[dst]);
    g_edge[p] = make_int2(src, __float_as_int(cf));
}

// ---------------- node aggregation core (warp-collective, 4x unroll) -------
__device__ __forceinline__ float4 agg_node(const __half* __restrict__ H,
                                           int node, int j, int sub,
                                           const float* __restrict__ bias) {
    int start = __ldg(&g_ptr[node]);
    int end   = __ldg(&g_ptr[node + 1]);
    const uint2* h2 = (const uint2*)H;
    float4 a0 = make_float4(0.f, 0.f, 0.f, 0.f);
    float4 a1 = make_float4(0.f, 0.f, 0.f, 0.f);
    float4 a2 = make_float4(0.f, 0.f, 0.f, 0.f);
    float4 a3 = make_float4(0.f, 0.f, 0.f, 0.f);
    int p = start + sub;
    for (; p + 6 < end; p += 8) {
        int2 e0 = __ldg(&g_edge[p]);
        int2 e1 = __ldg(&g_edge[p + 2]);
        int2 e2 = __ldg(&g_edge[p + 4]);
        int2 e3 = __ldg(&g_edge[p + 6]);
        HPack v0, v1, v2, v3;
        v0.u = __ldg(h2 + (size_t)e0.x * 16 + j);
        v1.u = __ldg(h2 + (size_t)e1.x * 16 + j);
        v2.u = __ldg(h2 + (size_t)e2.x * 16 + j);
        v3.u = __ldg(h2 + (size_t)e3.x * 16 + j);
        float c0 = __int_as_float(e0.y), c1 = __int_as_float(e1.y);
        float c2 = __int_as_float(e2.y), c3 = __int_as_float(e3.y);
        float2 fa, fb;
        fa = __half22float2(v0.h[0]); fb = __half22float2(v0.h[1]);
        a0.x += fa.x * c0; a0.y += fa.y * c0; a0.z += fb.x * c0; a0.w += fb.y * c0;
        fa = __half22float2(v1.h[0]); fb = __half22float2(v1.h[1]);
        a1.x += fa.x * c1; a1.y += fa.y * c1; a1.z += fb.x * c1; a1.w += fb.y * c1;
        fa = __half22float2(v2.h[0]); fb = __half22float2(v2.h[1]);
        a2.x += fa.x * c2; a2.y += fa.y * c2; a2.z += fb.x * c2; a2.w += fb.y * c2;
        fa = __half22float2(v3.h[0]); fb = __half22float2(v3.h[1]);
        a3.x += fa.x * c3; a3.y += fa.y * c3; a3.z += fb.x * c3; a3.w += fb.y * c3;
    }
    for (; p < end; p += 2) {
        int2 e0 = __ldg(&g_edge[p]);
        float c0 = __int_as_float(e0.y);
        HPack v0;
        v0.u = __ldg(h2 + (size_t)e0.x * 16 + j);
        float2 fa = __half22float2(v0.h[0]), fb = __half22float2(v0.h[1]);
        a0.x += fa.x * c0; a0.y += fa.y * c0; a0.z += fb.x * c0; a0.w += fb.y * c0;
    }
    a0.x += a1.x + a2.x + a3.x;
    a0.y += a1.y + a2.y + a3.y;
    a0.z += a1.z + a2.z + a3.z;
    a0.w += a1.w + a2.w + a3.w;
    a0.x += __shfl_down_sync(0xffffffffu, a0.x, 16);
    a0.y += __shfl_down_sync(0xffffffffu, a0.y, 16);
    a0.z += __shfl_down_sync(0xffffffffu, a0.z, 16);
    a0.w += __shfl_down_sync(0xffffffffu, a0.w, 16);
    float4 r = make_float4(0.f, 0.f, 0.f, 0.f);
    if (sub == 0) {
        float dn = __ldg(&g_dinv[node]);
        float c = dn * dn;
        HPack hs;
        hs.u = __ldg((const uint2*)H + (size_t)node * 16 + j);
        float2 ha = __half22float2(hs.h[0]), hb = __half22float2(hs.h[1]);
        float4 b = __ldg((const float4*)bias + j);
        r.x = fmaxf(a0.x + ha.x * c + b.x, 0.f);
        r.y = fmaxf(a0.y + ha.y * c + b.y, 0.f);
        r.z = fmaxf(a0.z + hb.x * c + b.z, 0.f);
        r.w = fmaxf(a0.w + hb.y * c + b.w, 0.f);
    }
    return r;
}

// ---------------- fused agg1 + gemm2(HMMA): reads g_h, writes g_h2 ---------
__global__ void k_mid(const float* __restrict__ bias, __half* __restrict__ Y) {
    const int AS = 72;    // padded halves per row
    __shared__ __align__(16) __half As[64 * AS];    // agg rows fp16 [m][k]
    __shared__ __align__(16) __half W2s[64 * AS];   // W2^T fp16 [n][k]
    int t = threadIdx.x;
    int warp = t >> 5, lane = t & 31;
    int j = lane & 15, sub = lane >> 4;
    int node0 = blockIdx.x * 64;

    // load W2t [64][64] -> padded smem
#pragma unroll
    for (int i = 0; i < 2; i++) {
        int idx = t + i * 256;
        int row = idx >> 3, c = idx & 7;
        ((float4*)W2s)[row * 9 + c] = ((const float4*)g_W2t)[row * 8 + c];
    }

    // aggregation: each warp owns 8 node rows; write fp16 into As
#pragma unroll 1
    for (int s = 0; s < 8; s++) {
        int row = warp * 8 + s;
        int node = node0 + row;
        float4 r = make_float4(0.f, 0.f, 0.f, 0.f);
        if (node < NN) r = agg_node(g_h, node, j, sub, bias);
        if (sub == 0) {
            HPack pk;
            pk.h[0] = __floats2half2_rn(r.x, r.y);
            pk.h[1] = __floats2half2_rn(r.z, r.w);
            *(uint2*)&As[row * AS + 4 * j] = pk.u;
        }
    }
    __syncthreads();

    // HMMA: [64m x 64k] @ W2t -> 64n
    int g = lane >> 2, tq = lane & 3;
    int mrow = (warp >> 1) * 16, ncol = (warp & 1) * 32;
    float acc[4][4];
#pragma unroll
    for (int jj = 0; jj < 4; jj++)
#pragma unroll
        for (int c = 0; c < 4; c++) acc[jj][c] = 0.f;

#pragma unroll
    for (int k0 = 0; k0 < HID / 16; k0++) {
        int kb = k0 * 16 + 2 * tq;
        unsigned a0 = *(const unsigned*)&As[(mrow + g) * AS + kb];
        unsigned a1 = *(const unsigned*)&As[(mrow + g + 8) * AS + kb];
        unsigned a2 = *(const unsigned*)&As[(mrow + g) * AS + kb + 8];
        unsigned a3 = *(const unsigned*)&As[(mrow + g + 8) * AS + kb + 8];
#pragma unroll
        for (int jj = 0; jj < 4; jj++) {
            int n = ncol + jj * 8 + g;
            unsigned b0 = *(const unsigned*)&W2s[n * AS + kb];
            unsigned b1 = *(const unsigned*)&W2s[n * AS + kb + 8];
            mma16816(acc[jj], a0, a1, a2, a3, b0, b1);
        }
    }
#pragma unroll
    for (int jj = 0; jj < 4; jj++) {
        int col = ncol + jj * 8 + 2 * tq;
        int n1 = node0 + mrow + g, n2 = n1 + 8;
        if (n1 < NN) {
            __half2 p = __floats2half2_rn(acc[jj][0], acc[jj][1]);
            *(__half2*)&Y[(size_t)n1 * HID + col] = p;
        }
        if (n2 < NN) {
            __half2 p = __floats2half2_rn(acc[jj][2], acc[jj][3]);
            *(__half2*)&Y[(size_t)n2 * HID + col] = p;
        }
    }
}

// ---------------- layer-2 aggregation + fused pool (reads g_h2) ------------
__global__ void k_aggpool(const float* __restrict__ bias,
                          const int* __restrict__ batch) {
    int warp = threadIdx.x >> 5, lane = threadIdx.x & 31;
    int j = lane & 15, sub = lane >> 4;
    int node = blockIdx.x * 8 + warp;
    if (node >= NN) return;
    float4 r = agg_node(g_h2, node, j, sub, bias);
    if (sub == 0) {
        int g = __ldg(&batch[node]);
        float4* p4 = (float4*)g_pool + (size_t)g * 16 + j;
        asm volatile("red.global.add.v4.f32 [%0], {%1, %2, %3, %4};"
                     :: "l"(p4), "f"(r.x), "f"(r.y), "f"(r.z), "f"(r.w)
                     : "memory");
    }
}

// ---------------- head -----------------------------------------------------
__global__ void k_head(const float* __restrict__ Wfc, const float* __restrict__ bfc,
                       float* __restrict__ out) {
    __shared__ float Wf[HID * NC];
    __shared__ float bf[NC];
    for (int i = threadIdx.x; i < HID * NC; i += blockDim.x) Wf[i] = Wfc[i];
    if (threadIdx.x < NC) bf[threadIdx.x] = bfc[threadIdx.x];
    __syncthreads();
    int g = blockIdx.x * blockDim.x + threadIdx.x;
    if (g >= NG) return;
    float inv = 1.0f / fmaxf((float)g_gcnt[g], 1.0f);
    float l[NC];
#pragma unroll
    for (int j = 0; j < NC; j++) l[j] = bf[j];
    for (int k = 0; k < HID; k++) {
        float pv = g_pool[g * HID + k] * inv;
#pragma unroll
        for (int j = 0; j < NC; j++) l[j] += pv * Wf[k * NC + j];
    }
    float m = l[0];
#pragma unroll
    for (int j = 1; j < NC; j++) m = fmaxf(m, l[j]);
    float s = 0.f;
#pragma unroll
    for (int j = 0; j < NC; j++) s += expf(l[j] - m);
    float lse = m + logf(s);
#pragma unroll
    for (int j = 0; j < NC; j++) out[g * NC + j] = l[j] - lse;
}

// ---------------------------------------------------------------------------
extern "C" void kernel_launch(void* const* d_in, const int* in_sizes, int n_in,
                              void* d_out, int out_size) {
    const float* x     = (const float*)d_in[0];
    const int*   ei    = (const int*)d_in[1];
    const int*   batch = (const int*)d_in[2];
    const float* W1    = (const float*)d_in[3];
    const float* b1    = (const float*)d_in[4];
    const float* W2    = (const float*)d_in[5];
    const float* b2    = (const float*)d_in[6];
    const float* Wfc   = (const float*)d_in[7];
    const float* bfc   = (const float*)d_in[8];
    float* out = (float*)d_out;

    // Resolve REAL device addresses (host shadow symbols are a silent ATS trap).
    void *p_degi, *p_gcnt, *p_pool, *p_h, *p_h2;
    cudaGetSymbolAddress(&p_degi, g_degi);
    cudaGetSymbolAddress(&p_gcnt, g_gcnt);
    cudaGetSymbolAddress(&p_pool, g_pool);
    cudaGetSymbolAddress(&p_h,    g_h);
    cudaGetSymbolAddress(&p_h2,   g_h2);
    __half* dh  = (__half*)p_h;
    __half* dh2 = (__half*)p_h2;

    cudaMemsetAsync(p_degi, 0, NN * sizeof(int));
    cudaMemsetAsync(p_gcnt, 0, NG * sizeof(int));
    cudaMemsetAsync(p_pool, 0, NG * HID * sizeof(float));

    // weight transpose/convert (tiny)
    k_prep<<<(DIN * HID + HID * HID + 255) / 256, 256>>>(W1, W2);

    // fused: gemm1(HMMA) + degree histogram + graph histogram
    k_front<<<GEMM1_BLKS + DEG4_BLKS + GCNT4_BLKS, 256>>>(x, ei, batch, dh);

    // CSR pointers + packed edge scatter
    k_scan1<<<SCAN_BLKS, 1024>>>();
    k_scan2<<<1, 128>>>();
    k_scan3<<<SCAN_BLKS, 1024>>>();
    k_scatter<<<(NE + 255) / 256, 256>>>(ei);

    // fused agg1 + gemm2(HMMA): reads g_h, writes g_h2
    k_mid<<<(NN + 63) / 64, 256>>>(b1, dh2);

    // layer-2 aggregation + fused pool (reads g_h2)
    k_aggpool<<<(NN + 7) / 8, 256>>>(b2, batch);

    // head
    k_head<<<1, NG>>>(Wfc, bfc, out);
}